// round 7
// baseline (speedup 1.0000x reference)
#include <cuda_runtime.h>
#include <cuda_bf16.h>

// Shapes fixed by setup_inputs: B=32, P=32, S=512
static constexpr int B   = 32;
static constexpr int P   = 32;
static constexpr int S   = 512;
static constexpr int PS  = P * S;                    // 16384
static constexpr size_t NOUT = (size_t)B * P * PS;   // 16777216 per output tensor

// One fused kernel: grid = B*P*16 blocks (one (b,p) per 16 blocks), 256 thr,
// 4 consecutive j per thread. Each thread recomputes both param sets from raw
// inputs (uniform broadcast loads, L1-hit; rsqrt is MUFU noise), forward-rotates
// the owner's local coords from coef, then inverse-rotates into p's frame.
__global__ void __launch_bounds__(256) fused_kernel(const float* __restrict__ shape,
                                                    const float* __restrict__ trans,
                                                    const float* __restrict__ quat,
                                                    const float* __restrict__ iou,
                                                    const float* __restrict__ coef,
                                                    float* __restrict__ tsdfOut,
                                                    float* __restrict__ weight,
                                                    float* __restrict__ tsdfGT) {
    int blk = blockIdx.x;            // 0..16383
    int bp  = blk >> 4;              // b*P + p
    int chunk = blk & 15;
    int b = bp >> 5;
    int p = bp & 31;

    int j0 = chunk * 1024 + threadIdx.x * 4;  // 4 consecutive j, same owner (S=512)
    int o  = j0 >> 9;
    int bo = (b << 5) + o;

    // ---- owner (b,o) params: normalized quat, shape, trans, vol ----
    float4 qo4 = *reinterpret_cast<const float4*>(&quat[bo * 4]);
    float oinv = rsqrtf(qo4.x * qo4.x + qo4.y * qo4.y + qo4.z * qo4.z + qo4.w * qo4.w);
    float ow = qo4.x * oinv, ox = qo4.y * oinv, oy = qo4.z * oinv, oz = qo4.w * oinv;
    float osx = shape[bo * 3 + 0];
    float osy = shape[bo * 3 + 1];
    float osz = shape[bo * 3 + 2];
    float otx = trans[bo * 3 + 0];
    float oty = trans[bo * 3 + 1];
    float otz = trans[bo * 3 + 2];
    float wv  = osx * osy * osz * iou[bo];    // vol[b, owner] -> weight value

    // ---- self (b,p) params: conjugated normalized quat, shape, trans, iou ----
    float4 qp4 = *reinterpret_cast<const float4*>(&quat[bp * 4]);
    float pinv = rsqrtf(qp4.x * qp4.x + qp4.y * qp4.y + qp4.z * qp4.z + qp4.w * qp4.w);
    float qw = qp4.x * pinv;
    float qx = -qp4.y * pinv;                 // conjugate -> inverse rotation
    float qy = -qp4.z * pinv;
    float qz = -qp4.w * pinv;
    float tx = trans[bp * 3 + 0];
    float ty = trans[bp * 3 + 1];
    float tz = trans[bp * 3 + 2];
    float sx = shape[bp * 3 + 0];
    float sy = shape[bp * 3 + 1];
    float sz = shape[bp * 3 + 2];
    float gate = (o != p) ? iou[bp] : 0.0f;

    // ---- coef: 4 j * 3 comps = 12 consecutive floats, 16B aligned ----
    const float* cptr = &coef[((size_t)b * PS + j0) * 3];
    float4 c0 = *reinterpret_cast<const float4*>(cptr + 0);
    float4 c1 = *reinterpret_cast<const float4*>(cptr + 4);
    float4 c2 = *reinterpret_cast<const float4*>(cptr + 8);
    float cc[12] = {c0.x, c0.y, c0.z, c0.w, c1.x, c1.y, c1.z, c1.w,
                    c2.x, c2.y, c2.z, c2.w};

    float4 outv;
    float* os = &outv.x;
#pragma unroll
    for (int k = 0; k < 4; k++) {
        // local = (2*coef-1) * shape_o ; forward rotate by owner quat ; + trans_o
        float vx = fmaf(2.0f, cc[k * 3 + 0], -1.0f) * osx;
        float vy = fmaf(2.0f, cc[k * 3 + 1], -1.0f) * osy;
        float vz = fmaf(2.0f, cc[k * 3 + 2], -1.0f) * osz;
        float uvx = oy * vz - oz * vy;
        float uvy = oz * vx - ox * vz;
        float uvz = ox * vy - oy * vx;
        float uuvx = oy * uvz - oz * uvy;
        float uuvy = oz * uvx - ox * uvz;
        float uuvz = ox * uvy - oy * uvx;
        float Px = vx + 2.0f * (ow * uvx + uuvx) + otx;
        float Py = vy + 2.0f * (ow * uvy + uuvy) + oty;
        float Pz = vz + 2.0f * (ow * uvz + uuvz) + otz;

        // p_rel = point - trans_p ; inverse rotate by conj(quat_p)
        float rx = Px - tx;
        float ry = Py - ty;
        float rz = Pz - tz;
        float wvx = qy * rz - qz * ry;
        float wvy = qz * rx - qx * rz;
        float wvz = qx * ry - qy * rx;
        float wwx = qy * wvz - qz * wvy;
        float wwy = qz * wvx - qx * wvz;
        float wwz = qx * wvy - qy * wvx;
        float lx = rx + 2.0f * (qw * wvx + wwx);
        float ly = ry + 2.0f * (qw * wvy + wwy);
        float lz = rz + 2.0f * (qw * wvz + wwz);

        float px = fmaxf(sx - fabsf(lx), 0.0f);
        float py = fmaxf(sy - fabsf(ly), 0.0f);
        float pz = fmaxf(sz - fabsf(lz), 0.0f);
        os[k] = (px * px + py * py + pz * pz) * gate;
    }

    size_t base = (size_t)bp * PS + j0;
    *reinterpret_cast<float4*>(&tsdfOut[base]) = outv;
    *reinterpret_cast<float4*>(&weight[base])  = make_float4(wv, wv, wv, wv);
    *reinterpret_cast<float4*>(&tsdfGT[base])  = make_float4(0.f, 0.f, 0.f, 0.f);
}

extern "C" void kernel_launch(void* const* d_in, const int* in_sizes, int n_in,
                              void* d_out, int out_size) {
    const float* shape = (const float*)d_in[0];
    const float* trans = (const float*)d_in[1];
    const float* quat  = (const float*)d_in[2];
    const float* iou   = (const float*)d_in[3];
    const float* coef  = (const float*)d_in[4];
    float* out = (float*)d_out;

    fused_kernel<<<B * P * 16, 256>>>(shape, trans, quat, iou, coef,
                                      out, out + NOUT, out + 2 * NOUT);
}